// round 11
// baseline (speedup 1.0000x reference)
#include <cuda_runtime.h>
#include <cstddef>

// GloVe loss — bucket sort by c>>5 (3 aux launches) + main kernel that
// finishes the exact sort IN SHARED MEMORY (by c&31) before gathering.
// grid=3125 -> ~3.5 waves, so each block's sort prologue overlaps other
// blocks' gather phase (fixes R8's single-wave serialization).
// Launches: hist -> scan -> scatter -> main.

static constexpr int EMB           = 300;
static constexpr int NV4           = EMB / 4;       // 75 float4 per row
static constexpr int BATCH_N       = 262144;

static constexpr int BUCKET_SHIFT  = 5;
static constexpr int NB            = 4096;          // covers 100000>>5 = 3125
static constexpr int NB_USED       = 3125;
static constexpr int SORT_CAP      = 192;           // avg bucket 84, sd ~9

static constexpr int STHREADS      = 512;
static constexpr int SCHUNK        = 2048;
static constexpr int SBLOCKS      = BATCH_N / SCHUNK;   // 128
static constexpr int SPT           = SCHUNK / STHREADS;  // 4

static constexpr int THREADS       = 256;
static constexpr int WARPS_PER_BLK = THREADS / 32;  // 8

// Replay-safe: g_cnt zeroed by scan after read; g_base fully rewritten by
// scan each launch; s_recs fully overwritten by scatter; g_acc/g_done reset
// by the last main block. Main only READS g_base.
__device__ int    g_cnt[NB];
__device__ int    g_base[NB];
__device__ int4   s_recs[BATCH_N];
__device__ double g_acc;
__device__ unsigned int g_done;

// ---- 1) histogram by c>>5 (smem-aggregated) ---------------------------------
__global__ __launch_bounds__(STHREADS) void glove_hist_kernel(
    const int* __restrict__ center)
{
    __shared__ int h[NB];
    const int tid  = threadIdx.x;
    const int idx0 = blockIdx.x * SCHUNK;
    for (int i = tid; i < NB; i += STHREADS) h[i] = 0;
    __syncthreads();
    #pragma unroll
    for (int k = 0; k < SPT; ++k) {
        const int c = __ldg(center + idx0 + k * STHREADS + tid);
        atomicAdd(&h[c >> BUCKET_SHIFT], 1);
    }
    __syncthreads();
    for (int b = tid; b < NB; b += STHREADS)
        if (h[b]) atomicAdd(&g_cnt[b], h[b]);
}

// ---- 2) exclusive scan over 4096 (1 block, 4/thread); re-zero counts --------
__global__ __launch_bounds__(1024) void glove_scan_kernel()
{
    __shared__ int tmp[1024];
    const int t = threadIdx.x;
    int v[4], s = 0;
    #pragma unroll
    for (int k = 0; k < 4; ++k) {
        v[k] = g_cnt[t * 4 + k];
        g_cnt[t * 4 + k] = 0;           // restore for next replay
        s += v[k];
    }
    tmp[t] = s;
    __syncthreads();
    #pragma unroll
    for (int off = 1; off < 1024; off <<= 1) {
        int u = (t >= off) ? tmp[t - off] : 0;
        __syncthreads();
        tmp[t] += u;
        __syncthreads();
    }
    int run = tmp[t] - s;
    #pragma unroll
    for (int k = 0; k < 4; ++k) {
        g_base[t * 4 + k] = run;
        run += v[k];
    }
}

// ---- 3) bucketed scatter (two-phase smem, bulk range reserve) ---------------
// After this kernel, g_base[b] == END offset of bucket b.
__global__ __launch_bounds__(STHREADS) void glove_scatter_kernel(
    const int*   __restrict__ center,
    const int*   __restrict__ outside,
    const float* __restrict__ coocs,
    const float* __restrict__ weighting)
{
    __shared__ int h[NB];
    __shared__ int base[NB];
    const int tid  = threadIdx.x;
    const int idx0 = blockIdx.x * SCHUNK;

    for (int i = tid; i < NB; i += STHREADS) h[i] = 0;
    __syncthreads();

    int c[SPT];
    #pragma unroll
    for (int k = 0; k < SPT; ++k) {
        c[k] = __ldg(center + idx0 + k * STHREADS + tid);
        atomicAdd(&h[c[k] >> BUCKET_SHIFT], 1);
    }
    __syncthreads();
    for (int b = tid; b < NB; b += STHREADS) {
        const int n = h[b];
        base[b] = n ? atomicAdd(&g_base[b], n) : 0;
    }
    __syncthreads();
    for (int i = tid; i < NB; i += STHREADS) h[i] = 0;   // reuse as cursors
    __syncthreads();

    #pragma unroll
    for (int k = 0; k < SPT; ++k) {
        const int i = idx0 + k * STHREADS + tid;
        const int b = c[k] >> BUCKET_SHIFT;
        const int off = atomicAdd(&h[b], 1);
        int4 rec;
        rec.x = c[k];
        rec.y = __ldg(outside + i);
        rec.z = __float_as_int(__ldg(coocs + i));
        rec.w = __float_as_int(__ldg(weighting + i));
        s_recs[base[b] + off] = rec;
    }
}

// ---- 4) main: smem exact-sort of one bucket + gather with center reuse ------
__global__ __launch_bounds__(THREADS, 6) void glove_main_kernel(
    const float* __restrict__ cemb,
    const float* __restrict__ oemb,
    const float* __restrict__ cbias,
    const float* __restrict__ obias,
    float*       __restrict__ out)
{
    __shared__ int4 srt[SORT_CAP];
    __shared__ int  cnt[32];
    __shared__ int  pos[32];
    __shared__ float sh[WARPS_PER_BLK];

    const int b    = blockIdx.x;
    const int tid  = threadIdx.x;
    const int lane = tid & 31;
    const int warp = tid >> 5;

    const int s = (b == 0) ? 0 : g_base[b - 1];
    const int n = g_base[b] - s;
    const bool fit = (n <= SORT_CAP);

    // Sort prologue: coalesced bucket load -> counting sort by c&31 in smem.
    if (tid < 32) cnt[tid] = 0;
    __syncthreads();
    int4 myrec[1];
    if (fit && tid < n) {
        myrec[0] = __ldg(&s_recs[s + tid]);
        atomicAdd(&cnt[myrec[0].x & 31], 1);
    }
    __syncthreads();
    if (tid < 32) {
        int x = cnt[tid];
        int incl = x;
        #pragma unroll
        for (int off = 1; off < 32; off <<= 1) {
            int u = __shfl_up_sync(0xffffffffu, incl, off);
            if (tid >= off) incl += u;
        }
        pos[tid] = incl - x;            // exclusive prefix = cursor
    }
    __syncthreads();
    if (fit && tid < n)
        srt[atomicAdd(&pos[myrec[0].x & 31], 1)] = myrec[0];
    __syncthreads();

    // Gather: each warp walks a contiguous sorted chunk.
    const float4* __restrict__ cemb4 = reinterpret_cast<const float4*>(cemb);
    const float4* __restrict__ oemb4 = reinterpret_cast<const float4*>(oemb);

    const int chunk = (n + WARPS_PER_BLK - 1) / WARPS_PER_BLK;
    const int i0    = warp * chunk;
    const int i1    = (i0 + chunk < n) ? (i0 + chunk) : n;

    float wsum = 0.0f;
    int   prev = -1;
    float4 a0, a1, a2;
    float  cb = 0.0f;
    a0 = a1 = a2 = make_float4(0.f, 0.f, 0.f, 0.f);

    for (int i = i0; i < i1; ++i) {
        const int4 rec = fit ? srt[i] : __ldg(&s_recs[s + i]);

        const unsigned oo = (unsigned)rec.y * (unsigned)NV4 + (unsigned)lane;
        float4 b0 = __ldg(oemb4 + oo);
        float4 b1 = __ldg(oemb4 + oo + 32);
        float4 b2 = make_float4(0.f, 0.f, 0.f, 0.f);
        if (lane < NV4 - 64) b2 = __ldg(oemb4 + oo + 64);
        const float obv = __ldg(obias + rec.y);

        if (rec.x != prev) {   // warp-uniform (sorted by center)
            const unsigned co = (unsigned)rec.x * (unsigned)NV4 + (unsigned)lane;
            a0 = __ldg(cemb4 + co);
            a1 = __ldg(cemb4 + co + 32);
            a2 = make_float4(0.f, 0.f, 0.f, 0.f);
            if (lane < NV4 - 64) a2 = __ldg(cemb4 + co + 64);
            cb = __ldg(cbias + rec.x);
            prev = rec.x;
        }

        float dot = a0.x * b0.x + a0.y * b0.y + a0.z * b0.z + a0.w * b0.w;
        dot      += a1.x * b1.x + a1.y * b1.y + a1.z * b1.z + a1.w * b1.w;
        dot      += a2.x * b2.x + a2.y * b2.y + a2.z * b2.z + a2.w * b2.w;

        #pragma unroll
        for (int off = 16; off; off >>= 1)
            dot += __shfl_xor_sync(0xffffffffu, dot, off);

        if (lane == 0) {
            const float err = dot + cb + obv - __int_as_float(rec.z);
            wsum += __int_as_float(rec.w) * err * err;
        }
    }

    if (lane == 0) sh[warp] = wsum;
    __syncthreads();

    if (tid == 0) {
        float sblk = 0.0f;
        #pragma unroll
        for (int i = 0; i < WARPS_PER_BLK; ++i) sblk += sh[i];
        atomicAdd(&g_acc, (double)sblk);

        __threadfence();
        const unsigned t = atomicAdd(&g_done, 1u);
        if (t == (unsigned)(NB_USED - 1)) {
            const double v = atomicAdd(&g_acc, 0.0);
            out[0] = (float)v;
            g_acc  = 0.0;
            g_done = 0u;
        }
    }
}

extern "C" void kernel_launch(void* const* d_in, const int* in_sizes, int n_in,
                              void* d_out, int out_size) {
    const int*   center    = (const int*)  d_in[0];
    const int*   outside   = (const int*)  d_in[1];
    const float* coocs     = (const float*)d_in[2];
    const float* weighting = (const float*)d_in[3];
    const float* cemb      = (const float*)d_in[4];
    const float* oemb      = (const float*)d_in[5];
    const float* cbias     = (const float*)d_in[6];
    const float* obias     = (const float*)d_in[7];
    float* out = (float*)d_out;

    glove_hist_kernel<<<SBLOCKS, STHREADS>>>(center);
    glove_scan_kernel<<<1, 1024>>>();
    glove_scatter_kernel<<<SBLOCKS, STHREADS>>>(center, outside, coocs, weighting);
    glove_main_kernel<<<NB_USED, THREADS>>>(cemb, oemb, cbias, obias, out);
}

// round 12
// speedup vs baseline: 1.5340x; 1.5340x over previous
#include <cuda_runtime.h>
#include <cstddef>

// GloVe loss — R7 structure (exact two-level counting sort by center:
// buckets c>>7, then in-bucket c&127) with a rebuilt, sync-light sort2.
// Launches: hist -> scan -> scatter -> sort2 -> main.

static constexpr int EMB           = 300;
static constexpr int NV4           = EMB / 4;       // 75 float4 per row
static constexpr int BATCH_N       = 262144;

static constexpr int BUCKET_SHIFT  = 7;
static constexpr int NB            = 1024;          // covers 100000>>7 = 782
static constexpr int NB_USED       = 782;
static constexpr int SORT_CAP      = 1024;          // bucket avg 335, sd ~18

static constexpr int STHREADS      = 512;
static constexpr int SCHUNK        = 2048;
static constexpr int SBLOCKS      = BATCH_N / SCHUNK;   // 128
static constexpr int SPT           = SCHUNK / STHREADS;  // 4

static constexpr int THREADS       = 256;
static constexpr int WARPS_PER_BLK = THREADS / 32;  // 8
static constexpr int ROWS_PER_WARP = 8;
static constexpr int MBLOCKS       = BATCH_N / (WARPS_PER_BLK * ROWS_PER_WARP); // 4096

// Replay-safe: g_cnt zeroed by scan after read; g_base fully rewritten by
// scan; s_recs fully overwritten; g_acc/g_done reset by last main block.
__device__ int    g_cnt[NB];
__device__ int    g_base[NB];
__device__ int4   s_recs[BATCH_N];
__device__ double g_acc;
__device__ unsigned int g_done;

// ---- 1) histogram by c>>7 ---------------------------------------------------
__global__ __launch_bounds__(STHREADS) void glove_hist_kernel(
    const int* __restrict__ center)
{
    __shared__ int h[NB];
    const int tid  = threadIdx.x;
    const int idx0 = blockIdx.x * SCHUNK;
    for (int i = tid; i < NB; i += STHREADS) h[i] = 0;
    __syncthreads();
    #pragma unroll
    for (int k = 0; k < SPT; ++k) {
        const int c = __ldg(center + idx0 + k * STHREADS + tid);
        atomicAdd(&h[c >> BUCKET_SHIFT], 1);
    }
    __syncthreads();
    for (int b = tid; b < NB; b += STHREADS)
        if (h[b]) atomicAdd(&g_cnt[b], h[b]);
}

// ---- 2) exclusive scan; re-zero counts for replay ---------------------------
__global__ __launch_bounds__(NB) void glove_scan_kernel()
{
    __shared__ int tmp[NB];
    const int t = threadIdx.x;
    const int v = g_cnt[t];
    g_cnt[t] = 0;
    tmp[t] = v;
    __syncthreads();
    #pragma unroll
    for (int off = 1; off < NB; off <<= 1) {
        int u = (t >= off) ? tmp[t - off] : 0;
        __syncthreads();
        tmp[t] += u;
        __syncthreads();
    }
    g_base[t] = tmp[t] - v;
}

// ---- 3) bucketed scatter ----------------------------------------------------
// After this kernel, g_base[b] == END offset of bucket b.
__global__ __launch_bounds__(STHREADS) void glove_scatter_kernel(
    const int*   __restrict__ center,
    const int*   __restrict__ outside,
    const float* __restrict__ coocs,
    const float* __restrict__ weighting)
{
    __shared__ int h[NB];
    __shared__ int base[NB];
    const int tid  = threadIdx.x;
    const int idx0 = blockIdx.x * SCHUNK;

    for (int i = tid; i < NB; i += STHREADS) h[i] = 0;
    __syncthreads();

    int c[SPT];
    #pragma unroll
    for (int k = 0; k < SPT; ++k) {
        c[k] = __ldg(center + idx0 + k * STHREADS + tid);
        atomicAdd(&h[c[k] >> BUCKET_SHIFT], 1);
    }
    __syncthreads();
    for (int b = tid; b < NB; b += STHREADS) {
        const int n = h[b];
        base[b] = n ? atomicAdd(&g_base[b], n) : 0;
    }
    __syncthreads();
    for (int i = tid; i < NB; i += STHREADS) h[i] = 0;   // reuse as cursors
    __syncthreads();

    #pragma unroll
    for (int k = 0; k < SPT; ++k) {
        const int i = idx0 + k * STHREADS + tid;
        const int b = c[k] >> BUCKET_SHIFT;
        const int off = atomicAdd(&h[b], 1);
        int4 rec;
        rec.x = c[k];
        rec.y = __ldg(outside + i);
        rec.z = __float_as_int(__ldg(coocs + i));
        rec.w = __float_as_int(__ldg(weighting + i));
        s_recs[base[b] + off] = rec;
    }
}

// ---- 3b) in-bucket counting sort by c&127 — sync-light rebuild --------------
// 512 threads; records held in registers (<=2/thread); 4-warp shfl scan of the
// 128 counters (3 __syncthreads total instead of 14+).
__global__ __launch_bounds__(512) void glove_sort2_kernel()
{
    __shared__ int cnt[128];
    __shared__ int pos[128];
    __shared__ int wsum[4];
    const int b    = blockIdx.x;
    const int tid  = threadIdx.x;
    const int lane = tid & 31;
    const int warp = tid >> 5;
    const int s    = (b == 0) ? 0 : g_base[b - 1];
    const int n    = g_base[b] - s;
    if (n <= 0 || n > SORT_CAP) return;   // perf-only fallback, ~never taken

    if (tid < 128) cnt[tid] = 0;
    __syncthreads();

    // Load records into registers (coalesced) + histogram.
    int4 r0, r1;
    const bool has0 = (tid < n);
    const bool has1 = (tid + 512 < n);
    if (has0) {
        r0 = __ldg(&s_recs[s + tid]);
        atomicAdd(&cnt[r0.x & 127], 1);
    }
    if (has1) {
        r1 = __ldg(&s_recs[s + tid + 512]);
        atomicAdd(&cnt[r1.x & 127], 1);
    }
    __syncthreads();

    // 4-warp shfl exclusive scan of 128 counters.
    if (warp < 4) {
        const int idx = warp * 32 + lane;
        const int x   = cnt[idx];
        int incl = x;
        #pragma unroll
        for (int off = 1; off < 32; off <<= 1) {
            int u = __shfl_up_sync(0xffffffffu, incl, off);
            if (lane >= off) incl += u;
        }
        if (lane == 31) wsum[warp] = incl;
        __syncwarp();
        // pos = exclusive-within-warp; warp offsets added after barrier
        pos[idx] = incl - x;
    }
    __syncthreads();
    if (tid < 128) {
        const int w = tid >> 5;
        int add = 0;
        #pragma unroll
        for (int k = 0; k < 3; ++k) if (k < w) add += wsum[k];
        pos[tid] += add;
    }
    __syncthreads();

    // Scatter back in sorted order.
    if (has0) s_recs[s + atomicAdd(&pos[r0.x & 127], 1)] = r0;
    if (has1) s_recs[s + atomicAdd(&pos[r1.x & 127], 1)] = r1;
}

// ---- 4) main gather with center-row register reuse (R7-proven) --------------
__global__ __launch_bounds__(THREADS, 6) void glove_main_kernel(
    const float* __restrict__ cemb,
    const float* __restrict__ oemb,
    const float* __restrict__ cbias,
    const float* __restrict__ obias,
    float*       __restrict__ out)
{
    const int lane  = threadIdx.x & 31;
    const int warp  = threadIdx.x >> 5;
    const int gwarp = blockIdx.x * WARPS_PER_BLK + warp;

    const float4* __restrict__ cemb4 = reinterpret_cast<const float4*>(cemb);
    const float4* __restrict__ oemb4 = reinterpret_cast<const float4*>(oemb);

    float wsum = 0.0f;
    int   prev = -1;
    float4 a0, a1, a2;
    float  cb = 0.0f;
    a0 = a1 = a2 = make_float4(0.f, 0.f, 0.f, 0.f);

    #pragma unroll 1
    for (int r = 0; r < ROWS_PER_WARP; ++r) {
        const int row = gwarp * ROWS_PER_WARP + r;
        const int4 rec = __ldg(&s_recs[row]);

        const unsigned oo = (unsigned)rec.y * (unsigned)NV4 + (unsigned)lane;
        float4 b0 = __ldg(oemb4 + oo);
        float4 b1 = __ldg(oemb4 + oo + 32);
        float4 b2 = make_float4(0.f, 0.f, 0.f, 0.f);
        if (lane < NV4 - 64) b2 = __ldg(oemb4 + oo + 64);
        const float obv = __ldg(obias + rec.y);

        if (rec.x != prev) {   // warp-uniform branch (records sorted by center)
            const unsigned co = (unsigned)rec.x * (unsigned)NV4 + (unsigned)lane;
            a0 = __ldg(cemb4 + co);
            a1 = __ldg(cemb4 + co + 32);
            a2 = make_float4(0.f, 0.f, 0.f, 0.f);
            if (lane < NV4 - 64) a2 = __ldg(cemb4 + co + 64);
            cb = __ldg(cbias + rec.x);
            prev = rec.x;
        }

        float dot = a0.x * b0.x + a0.y * b0.y + a0.z * b0.z + a0.w * b0.w;
        dot      += a1.x * b1.x + a1.y * b1.y + a1.z * b1.z + a1.w * b1.w;
        dot      += a2.x * b2.x + a2.y * b2.y + a2.z * b2.z + a2.w * b2.w;

        #pragma unroll
        for (int off = 16; off; off >>= 1)
            dot += __shfl_xor_sync(0xffffffffu, dot, off);

        if (lane == 0) {
            const float err = dot + cb + obv - __int_as_float(rec.z);
            wsum += __int_as_float(rec.w) * err * err;
        }
    }

    __shared__ float sh[WARPS_PER_BLK];
    if (lane == 0) sh[warp] = wsum;
    __syncthreads();

    if (threadIdx.x == 0) {
        float s = 0.0f;
        #pragma unroll
        for (int i = 0; i < WARPS_PER_BLK; ++i) s += sh[i];
        atomicAdd(&g_acc, (double)s);

        __threadfence();
        const unsigned t = atomicAdd(&g_done, 1u);
        if (t == (unsigned)(MBLOCKS - 1)) {
            const double v = atomicAdd(&g_acc, 0.0);
            out[0] = (float)v;
            g_acc  = 0.0;
            g_done = 0u;
        }
    }
}

extern "C" void kernel_launch(void* const* d_in, const int* in_sizes, int n_in,
                              void* d_out, int out_size) {
    const int*   center    = (const int*)  d_in[0];
    const int*   outside   = (const int*)  d_in[1];
    const float* coocs     = (const float*)d_in[2];
    const float* weighting = (const float*)d_in[3];
    const float* cemb      = (const float*)d_in[4];
    const float* oemb      = (const float*)d_in[5];
    const float* cbias     = (const float*)d_in[6];
    const float* obias     = (const float*)d_in[7];
    float* out = (float*)d_out;

    glove_hist_kernel<<<SBLOCKS, STHREADS>>>(center);
    glove_scan_kernel<<<1, NB>>>();
    glove_scatter_kernel<<<SBLOCKS, STHREADS>>>(center, outside, coocs, weighting);
    glove_sort2_kernel<<<NB_USED, 512>>>();
    glove_main_kernel<<<MBLOCKS, THREADS>>>(cemb, oemb, cbias, obias, out);
}